// round 14
// baseline (speedup 1.0000x reference)
#include <cuda_runtime.h>
#include <cuda_fp16.h>
#include <math.h>
#include <float.h>
#include <stdint.h>

// Problem dims (fixed by the reference)
#define BB  2
#define SS  2048
#define DD  1024
#define HH  16
#define HD  64
#define BH  (BB*HH)          // 32
#define MTOK (BB*SS)         // 4096

// Scratch (device globals: allocation-free rule)
__device__ __half g_Qh[BH*SS*HD];   // [bh][s][hd] (half, pre-scaled by 0.125*log2e)
__device__ __half g_Kh[BH*SS*HD];
__device__ __half g_Vh[BH*SS*HD];
__device__ __half g_Oh[MTOK*DD];    // [tok][d] attn out (half)
__device__ __half g_Xh[MTOK*DD];    // X rounded to half
__device__ __half g_Wqh[DD*DD], g_Wkh[DD*DD], g_Wvh[DD*DD], g_Woh[DD*DD];
// Per-batch last key tile (64-key granularity) containing any unmasked key.
// atomicMax against a constant mask is idempotent -> deterministic across replays.
__device__ int g_ktlim[BB] = {0, 0};

// ---------------------------------------------------------------------------
// Helpers
// ---------------------------------------------------------------------------
__device__ __forceinline__ float ex2(float x) {
    float y; asm("ex2.approx.f32 %0, %1;" : "=f"(y) : "f"(x)); return y;
}
__device__ __forceinline__ uint32_t smem_u32(const void* p) {
    uint32_t a;
    asm("{ .reg .u64 t; cvta.to.shared.u64 t, %1; cvt.u32.u64 %0, t; }" : "=r"(a) : "l"(p));
    return a;
}
__device__ __forceinline__ void cpa16(uint32_t dst, const void* src) {
    asm volatile("{ .reg .u64 g; cvta.to.global.u64 g, %1; cp.async.cg.shared.global [%0], [g], 16; }"
                 :: "r"(dst), "l"(src));
}
#define CPA_COMMIT() asm volatile("cp.async.commit_group;" ::: "memory")
#define CPA_WAIT0()  asm volatile("cp.async.wait_group 0;" ::: "memory")
#define CPA_WAIT1()  asm volatile("cp.async.wait_group 1;" ::: "memory")

// swizzled byte address: 128B rows, 16B chunks, chunk ^= row&7
__device__ __forceinline__ uint32_t swz(uint32_t base, int row, int chunk) {
    return base + (uint32_t)(row * 128) + (uint32_t)(((chunk ^ (row & 7)) << 4));
}

__device__ __forceinline__ void ldm_x4(uint32_t& r0, uint32_t& r1, uint32_t& r2, uint32_t& r3, uint32_t a) {
    asm volatile("ldmatrix.sync.aligned.m8n8.x4.shared.b16 {%0,%1,%2,%3}, [%4];"
                 : "=r"(r0), "=r"(r1), "=r"(r2), "=r"(r3) : "r"(a));
}
__device__ __forceinline__ void ldm_x4t(uint32_t& r0, uint32_t& r1, uint32_t& r2, uint32_t& r3, uint32_t a) {
    asm volatile("ldmatrix.sync.aligned.m8n8.x4.trans.shared.b16 {%0,%1,%2,%3}, [%4];"
                 : "=r"(r0), "=r"(r1), "=r"(r2), "=r"(r3) : "r"(a));
}

// D += A * B  (m16n8k16 fp16 inputs, f32 accum)
__device__ __forceinline__ void mma_f16(float* d, const uint32_t* a, uint32_t b0, uint32_t b1) {
    asm volatile(
        "mma.sync.aligned.m16n8k16.row.col.f32.f16.f16.f32 "
        "{%0,%1,%2,%3},{%4,%5,%6,%7},{%8,%9},{%0,%1,%2,%3};"
        : "+f"(d[0]), "+f"(d[1]), "+f"(d[2]), "+f"(d[3])
        : "r"(a[0]), "r"(a[1]), "r"(a[2]), "r"(a[3]), "r"(b0), "r"(b1));
}

__device__ __forceinline__ uint32_t pack_h2(float lo, float hi) {
    __half2 h = __floats2half2_rn(lo, hi);
    return *(uint32_t*)&h;
}

// ---------------------------------------------------------------------------
// Prepass: convert X + 4 weight matrices to half (one launch).
// Extra block (last) scans the key-padding mask to compute g_ktlim[b].
// ---------------------------------------------------------------------------
#define XQUAD (MTOK*DD/4)      // 1048576
#define WQUAD (DD*DD/4)        // 262144
#define PREP_BLOCKS ((XQUAD + 4 * WQUAD) / 256)   // 8192
__global__ void prep_h(const float* __restrict__ X,
                       const float* __restrict__ wq, const float* __restrict__ wk,
                       const float* __restrict__ wv, const float* __restrict__ wo,
                       const int* __restrict__ kpm)
{
    if (blockIdx.x == PREP_BLOCKS) {
        // mask scan: thread t handles batch t>>5, key tile t&31
        const int t = threadIdx.x;
        if (t < BB * (SS / 64)) {
            const int b    = t >> 5;
            const int tile = t & 31;
            const int* mp = kpm + (size_t)b * SS + tile * 64;
            bool any = false;
            for (int j = 0; j < 64; j++) any |= (mp[j] == 0);
            if (any) atomicMax(&g_ktlim[b], tile);
        }
        return;
    }
    const int i = blockIdx.x * blockDim.x + threadIdx.x;   // 0 .. XQUAD+4*WQUAD-1
    const float* s; __half* d; int loc;
    if (i < XQUAD) { s = X; d = g_Xh; loc = i; }
    else {
        const int j = i - XQUAD;
        const int reg = j >> 18;
        loc = j & (WQUAD - 1);
        s = (reg == 0) ? wq : (reg == 1) ? wk : (reg == 2) ? wv : wo;
        d = (reg == 0) ? g_Wqh : (reg == 1) ? g_Wkh : (reg == 2) ? g_Wvh : g_Woh;
    }
    float4 v = ((const float4*)s)[loc];
    uint2 u;
    u.x = pack_h2(v.x, v.y);
    u.y = pack_h2(v.z, v.w);
    ((uint2*)d)[loc] = u;
}

// ---------------------------------------------------------------------------
// fp16 NT GEMM (R8 config — measured best): C[m][n] = sum_k A[m][k]*W[n][k] + bias[n]
// Block 128x128, k-chunk 64 halves (128B swizzled rows), 3-stage cp.async.
// 256 thr = 8 warps (4m x 2n), warp tile 32x64. ldmatrix operand loads.
// HEADOUT 0: fp32 row-major.  1: half head-major.  2: half head-major *qscale.
// ---------------------------------------------------------------------------
#define GST  16384u                    // one matrix per stage: 128*128B
#define GSTG 32768u
#define GSM_TOTAL (3 * 32768)          // 98304

template<int HEADOUT>
__device__ __forceinline__ void gemm_body(
    const __half* __restrict__ A, const __half* __restrict__ W,
    const float* __restrict__ bias, void* __restrict__ Cout,
    int m0, int n0, char* smem)
{
    const uint32_t sb = smem_u32(smem);
    const int tid  = threadIdx.x;
    const int warp = tid >> 5;
    const int lane = tid & 31;
    const int r = lane >> 2;
    const int c = lane & 3;
    const int wm = (warp & 3) * 32;
    const int wn = (warp >> 2) * 64;
    const int lrow = (lane & 7) + (lane & 8);   // ldmatrix row-within-16 for this lane
    const int lsel = lane >> 4;                 // ldmatrix chunk-half select

    float acc[2][8][4];
#pragma unroll
    for (int mt = 0; mt < 2; mt++)
#pragma unroll
        for (int nt = 0; nt < 8; nt++)
#pragma unroll
            for (int i = 0; i < 4; i++) acc[mt][nt][i] = 0.f;

    auto fill = [&](int st, int k0) {
        const uint32_t base = sb + (uint32_t)st * GSTG;
#pragma unroll
        for (int t = 0; t < 4; t++) {
            const int idx = tid + t * 256;     // 0..1023
            const int row = idx >> 3;          // 0..127
            const int ch  = idx & 7;           // 16B chunk = 8 halves
            cpa16(swz(base, row, ch),       A + (size_t)(m0 + row) * DD + k0 + ch * 8);
            cpa16(swz(base + GST, row, ch), W + (size_t)(n0 + row) * DD + k0 + ch * 8);
        }
        CPA_COMMIT();
    };

    fill(0, 0);
    fill(1, 64);

    int st = 0, st2 = 2;
    for (int i = 0; i < 16; i++) {
        if (i + 1 < 16) { CPA_WAIT1(); } else { CPA_WAIT0(); }
        __syncthreads();
        if (i + 2 < 16) fill(st2, (i + 2) * 64);

        const uint32_t Ab = sb + (uint32_t)st * GSTG;
        const uint32_t Bb = Ab + GST;

#pragma unroll
        for (int ks = 0; ks < 4; ks++) {       // 4 x k16
            const int ch = ks * 2 + lsel;
            uint32_t af[2][4];
#pragma unroll
            for (int mt = 0; mt < 2; mt++)
                ldm_x4(af[mt][0], af[mt][1], af[mt][2], af[mt][3],
                       swz(Ab, wm + mt * 16 + lrow, ch));
            uint32_t bf[8][2];
#pragma unroll
            for (int np = 0; np < 4; np++) {
                uint32_t r0, r1, r2, r3;
                ldm_x4(r0, r1, r2, r3, swz(Bb, wn + np * 16 + lrow, ch));
                bf[2*np][0] = r0; bf[2*np][1] = r2;
                bf[2*np+1][0] = r1; bf[2*np+1][1] = r3;
            }
#pragma unroll
            for (int mt = 0; mt < 2; mt++)
#pragma unroll
                for (int nt = 0; nt < 8; nt++)
                    mma_f16(acc[mt][nt], af[mt], bf[nt][0], bf[nt][1]);
        }
        st  = (st  == 2) ? 0 : st  + 1;
        st2 = (st2 == 2) ? 0 : st2 + 1;
    }

#pragma unroll
    for (int mt = 0; mt < 2; mt++) {
        const int m_lo = m0 + wm + mt * 16 + r;
        const int m_hi = m_lo + 8;
#pragma unroll
        for (int nt = 0; nt < 8; nt++) {
            const int ng = n0 + wn + nt * 8 + 2 * c;
            const float b0 = bias[ng], b1 = bias[ng + 1];
            if (HEADOUT) {
                const float sc = (HEADOUT == 2) ? 0.18033688011112042f : 1.f;  // 0.125*log2(e)
                const uint32_t lo = pack_h2((acc[mt][nt][0] + b0) * sc, (acc[mt][nt][1] + b1) * sc);
                const uint32_t hi = pack_h2((acc[mt][nt][2] + b0) * sc, (acc[mt][nt][3] + b1) * sc);
                const int h  = ng >> 6;
                const int hd = ng & 63;
                const int blo = m_lo >> 11, slo = m_lo & 2047;
                const int bhi = m_hi >> 11, shi = m_hi & 2047;
                __half* Ch = (__half*)Cout;
                *(uint32_t*)&Ch[(((size_t)(blo * HH + h) * SS) + slo) * HD + hd] = lo;
                *(uint32_t*)&Ch[(((size_t)(bhi * HH + h) * SS) + shi) * HD + hd] = hi;
            } else {
                float* Cf = (float*)Cout;
                *(float2*)&Cf[(size_t)m_lo * DD + ng] = make_float2(acc[mt][nt][0] + b0, acc[mt][nt][1] + b1);
                *(float2*)&Cf[(size_t)m_hi * DD + ng] = make_float2(acc[mt][nt][2] + b0, acc[mt][nt][3] + b1);
            }
        }
    }
}

// Fused QKV: grid (24, 32); virtual n picks matrix. Q scaled.
// K/V blocks whose 128 tokens are ALL mask-padded are skipped (validated R12/R13).
__global__ __launch_bounds__(256, 2)
void gemm_qkv(const float* __restrict__ bq, const float* __restrict__ bk,
              const float* __restrict__ bv, const int* __restrict__ kpm)
{
    extern __shared__ char smem[];
    const int n0v   = blockIdx.x * 128;
    const int which = n0v >> 10;
    const int n0    = n0v & 1023;
    const int m0    = blockIdx.y * 128;
    if (which != 0) {
        const int b_ = m0 >> 11;
        const int s_ = m0 & 2047;
        const int pv = kpm[(size_t)b_ * SS + s_ + (threadIdx.x & 127)];
        if (__syncthreads_and(pv != 0)) return;   // all 128 tokens padded
    }
    if (which == 0)
        gemm_body<2>(g_Xh, g_Wqh, bq, g_Qh, m0, n0, smem);
    else if (which == 1)
        gemm_body<1>(g_Xh, g_Wkh, bk, g_Kh, m0, n0, smem);
    else
        gemm_body<1>(g_Xh, g_Wvh, bv, g_Vh, m0, n0, smem);
}

// Output projection: A = g_Oh, exact fp32 out.
__global__ __launch_bounds__(256, 2)
void gemm_out(const float* __restrict__ bo, float* __restrict__ Cout)
{
    extern __shared__ char smem[];
    gemm_body<0>(g_Oh, g_Woh, bo, Cout, blockIdx.y * 128, blockIdx.x * 128, smem);
}

// ---------------------------------------------------------------------------
// Flash attention, fp16 mma + ldmatrix, 64-key tiles, 2-stage cp.async,
// base-2 softmax. Block: 64 q rows of one (b,h), 128 thr = 4 warps x 16 rows.
// kt range clamped to the last unmasked key tile (g_ktlim, data-driven).
// ---------------------------------------------------------------------------
#define AKOFF 0u
#define AVOFF 8192u
#define AMOFF 16384u
#define ASTG  16640u
#define APOFF 33280u
#define ASM_TOTAL (33280 + 8192)    // 41472

__global__ __launch_bounds__(128, 3)
void attn_h(const int* __restrict__ kpm)
{
    extern __shared__ char smem[];
    const uint32_t sb = smem_u32(smem);

    const int qt = gridDim.x - 1 - blockIdx.x;   // heavy causal blocks first
    const int bh = blockIdx.y;
    const int b_ = bh >> 4;
    const int h  = bh & 15;
    const int tid  = threadIdx.x;
    const int warp = tid >> 5;
    const int lane = tid & 31;
    const int r = lane >> 2;
    const int c = lane & 3;
    const int lrow = (lane & 7) + (lane & 8);
    const int lsel = lane >> 4;
    const int q0 = qt * 64;
    const int qr = warp * 16;
    const int qg_lo = q0 + qr + r;
    const int qg_hi = qg_lo + 8;

    auto fill = [&](int st, int kt) {
        const int kbase = kt * 64;
        const uint32_t base = sb + (uint32_t)st * ASTG;
#pragma unroll
        for (int i = 0; i < 4; i++) {
            const int idx = tid + i * 128;   // 0..511
            const int kr  = idx >> 3;        // 0..63
            const int ch  = idx & 7;
            cpa16(swz(base + AKOFF, kr, ch), g_Kh + (size_t)(bh * SS + kbase + kr) * HD + ch * 8);
            cpa16(swz(base + AVOFF, kr, ch), g_Vh + (size_t)(bh * SS + kbase + kr) * HD + ch * 8);
        }
        if (tid < 16)
            cpa16(base + AMOFF + tid * 16, kpm + (size_t)b_ * SS + kbase + tid * 4);
        CPA_COMMIT();
    };

    // Q fragments (half, pre-scaled): qf[ks][0..3] for k16 steps
    uint32_t qf[4][4];
    {
        const __half* qlo = g_Qh + (size_t)(bh * SS + qg_lo) * HD;
        const __half* qhi = g_Qh + (size_t)(bh * SS + qg_hi) * HD;
#pragma unroll
        for (int ks = 0; ks < 4; ks++) {
            qf[ks][0] = *(const uint32_t*)&qlo[ks * 16 + 2 * c];
            qf[ks][1] = *(const uint32_t*)&qhi[ks * 16 + 2 * c];
            qf[ks][2] = *(const uint32_t*)&qlo[ks * 16 + 2 * c + 8];
            qf[ks][3] = *(const uint32_t*)&qhi[ks * 16 + 2 * c + 8];
        }
    }

    float o[8][4];
#pragma unroll
    for (int nt = 0; nt < 8; nt++)
#pragma unroll
        for (int i = 0; i < 4; i++) o[nt][i] = 0.f;
    float m_lo = -1e30f, m_hi = -1e30f, l_lo = 0.f, l_hi = 0.f;

    // clamp to last unmasked key tile: tiles beyond contribute nothing
    const int kt_max = min(qt, g_ktlim[b_]);
    fill(0, 0);

    for (int kt = 0; kt <= kt_max; kt++) {
        CPA_WAIT0();
        __syncthreads();
        if (kt + 1 <= kt_max) fill((kt + 1) & 1, kt + 1);

        const uint32_t base = sb + (uint32_t)(kt & 1) * ASTG;
        const uint32_t Kb = base + AKOFF;
        const uint32_t Vb = base + AVOFF;
        const int* mk = (const int*)(smem + (kt & 1) * ASTG + AMOFF);
        const uint32_t Pb = sb + APOFF;

        const int kbase = kt * 64;
        const bool mymask = (mk[lane] != 0) || (mk[lane + 32] != 0);
        const int  skip = __all_sync(0xffffffffu, (mk[lane] != 0) && (mk[lane + 32] != 0));
        const int  anym = __any_sync(0xffffffffu, mymask);

        if (!skip) {
            // ---- scores: S = Q K^T (log2 domain) ----
            float s[8][4];
#pragma unroll
            for (int nt = 0; nt < 8; nt++)
#pragma unroll
                for (int i = 0; i < 4; i++) s[nt][i] = 0.f;
#pragma unroll
            for (int ks = 0; ks < 4; ks++) {
                const int ch = ks * 2 + lsel;
                uint32_t bf[8][2];
#pragma unroll
                for (int np = 0; np < 4; np++) {
                    uint32_t r0, r1, r2, r3;
                    ldm_x4(r0, r1, r2, r3, swz(Kb, np * 16 + lrow, ch));
                    bf[2*np][0] = r0; bf[2*np][1] = r2;
                    bf[2*np+1][0] = r1; bf[2*np+1][1] = r3;
                }
#pragma unroll
                for (int nt = 0; nt < 8; nt++)
                    mma_f16(s[nt], qf[ks], bf[nt][0], bf[nt][1]);
            }

            // ---- mask + row max ----
            float mloc_lo = -1e30f, mloc_hi = -1e30f;
            if (kt < qt && !anym) {
#pragma unroll
                for (int nt = 0; nt < 8; nt++) {
                    mloc_lo = fmaxf(mloc_lo, fmaxf(s[nt][0], s[nt][1]));
                    mloc_hi = fmaxf(mloc_hi, fmaxf(s[nt][2], s[nt][3]));
                }
            } else {
#pragma unroll
                for (int nt = 0; nt < 8; nt++) {
                    const int kc0 = nt * 8 + 2 * c;
                    const bool bad0 = mk[kc0] != 0;
                    const bool bad1 = mk[kc0 + 1] != 0;
                    const int kg0 = kbase + kc0, kg1 = kg0 + 1;
                    s[nt][0] = (bad0 || kg0 > qg_lo) ? -1e30f : s[nt][0];
                    s[nt][1] = (bad1 || kg1 > qg_lo) ? -1e30f : s[nt][1];
                    s[nt][2] = (bad0 || kg0 > qg_hi) ? -1e30f : s[nt][2];
                    s[nt][3] = (bad1 || kg1 > qg_hi) ? -1e30f : s[nt][3];
                    mloc_lo = fmaxf(mloc_lo, fmaxf(s[nt][0], s[nt][1]));
                    mloc_hi = fmaxf(mloc_hi, fmaxf(s[nt][2], s[nt][3]));
                }
            }
            mloc_lo = fmaxf(mloc_lo, __shfl_xor_sync(0xffffffffu, mloc_lo, 1));
            mloc_lo = fmaxf(mloc_lo, __shfl_xor_sync(0xffffffffu, mloc_lo, 2));
            mloc_hi = fmaxf(mloc_hi, __shfl_xor_sync(0xffffffffu, mloc_hi, 1));
            mloc_hi = fmaxf(mloc_hi, __shfl_xor_sync(0xffffffffu, mloc_hi, 2));

            const float mn_lo = fmaxf(m_lo, mloc_lo);
            const float mn_hi = fmaxf(m_hi, mloc_hi);
            const float a_lo = ex2(m_lo - mn_lo);
            const float a_hi = ex2(m_hi - mn_hi);
            m_lo = mn_lo; m_hi = mn_hi;

            // exp2 + row sums + P -> half in smem (swizzled, ldmatrix layout)
            float ps_lo = 0.f, ps_hi = 0.f;
#pragma unroll
            for (int nt = 0; nt < 8; nt++) {
                s[nt][0] = ex2(s[nt][0] - mn_lo);
                s[nt][1] = ex2(s[nt][1] - mn_lo);
                s[nt][2] = ex2(s[nt][2] - mn_hi);
                s[nt][3] = ex2(s[nt][3] - mn_hi);
                ps_lo += s[nt][0] + s[nt][1];
                ps_hi += s[nt][2] + s[nt][3];
                const int row0 = qr + r, row1 = qr + r + 8;
                *(uint32_t*)(smem + (swz(Pb, row0, nt) - sb) + 4 * c) = pack_h2(s[nt][0], s[nt][1]);
                *(uint32_t*)(smem + (swz(Pb, row1, nt) - sb) + 4 * c) = pack_h2(s[nt][2], s[nt][3]);
            }
            ps_lo += __shfl_xor_sync(0xffffffffu, ps_lo, 1);
            ps_lo += __shfl_xor_sync(0xffffffffu, ps_lo, 2);
            ps_hi += __shfl_xor_sync(0xffffffffu, ps_hi, 1);
            ps_hi += __shfl_xor_sync(0xffffffffu, ps_hi, 2);
            l_lo = a_lo * l_lo + ps_lo;
            l_hi = a_hi * l_hi + ps_hi;

#pragma unroll
            for (int nt = 0; nt < 8; nt++) {
                o[nt][0] *= a_lo; o[nt][1] *= a_lo;
                o[nt][2] *= a_hi; o[nt][3] *= a_hi;
            }
            __syncwarp();

            // ---- O += P V ----
#pragma unroll
            for (int ks = 0; ks < 4; ks++) {
                uint32_t af[4];
                ldm_x4(af[0], af[1], af[2], af[3],
                       swz(Pb, qr + lrow, ks * 2 + lsel));
                uint32_t bf[8][2];
#pragma unroll
                for (int np = 0; np < 4; np++) {
                    uint32_t r0, r1, r2, r3;
                    ldm_x4t(r0, r1, r2, r3,
                            swz(Vb, ks * 16 + lrow, 2 * np + lsel));
                    bf[2*np][0] = r0; bf[2*np][1] = r1;
                    bf[2*np+1][0] = r2; bf[2*np+1][1] = r3;
                }
#pragma unroll
                for (int nt = 0; nt < 8; nt++)
                    mma_f16(o[nt], af, bf[nt][0], bf[nt][1]);
            }
            __syncwarp();
        }
    }

    // ---- epilogue: normalize, convert to half, store head-major into g_Oh ----
    const float inv_lo = 1.f / l_lo;
    const float inv_hi = 1.f / l_hi;
    __half* olo = g_Oh + (size_t)(b_ * SS + qg_lo) * DD + h * HD;
    __half* ohi = g_Oh + (size_t)(b_ * SS + qg_hi) * DD + h * HD;
#pragma unroll
    for (int nt = 0; nt < 8; nt++) {
        const int dc = nt * 8 + 2 * c;
        *(uint32_t*)&olo[dc] = pack_h2(o[nt][0] * inv_lo, o[nt][1] * inv_lo);
        *(uint32_t*)&ohi[dc] = pack_h2(o[nt][2] * inv_hi, o[nt][3] * inv_hi);
    }
}

// ---------------------------------------------------------------------------
// Launch
// Inputs: 0:X 1:key_padding_mask 2:Wq 3:bq 4:Wk 5:bk 6:Wv 7:bv 8:Wo 9:bo
// ---------------------------------------------------------------------------
extern "C" void kernel_launch(void* const* d_in, const int* in_sizes, int n_in,
                              void* d_out, int out_size)
{
    const float* X   = (const float*)d_in[0];
    const int*   kpm = (const int*)  d_in[1];
    const float* Wq  = (const float*)d_in[2];
    const float* bq  = (const float*)d_in[3];
    const float* Wk  = (const float*)d_in[4];
    const float* bk  = (const float*)d_in[5];
    const float* Wv  = (const float*)d_in[6];
    const float* bv  = (const float*)d_in[7];
    const float* Wo  = (const float*)d_in[8];
    const float* bo  = (const float*)d_in[9];
    float* out = (float*)d_out;

    cudaFuncSetAttribute(gemm_qkv, cudaFuncAttributeMaxDynamicSharedMemorySize, GSM_TOTAL);
    cudaFuncSetAttribute(gemm_out, cudaFuncAttributeMaxDynamicSharedMemorySize, GSM_TOTAL);
    cudaFuncSetAttribute(attn_h,   cudaFuncAttributeMaxDynamicSharedMemorySize, ASM_TOTAL);

    // Prepass: X + 4 weights -> half; last block computes g_ktlim from the mask
    prep_h<<<PREP_BLOCKS + 1, 256>>>(X, Wq, Wk, Wv, Wo, kpm);

    // Fused QKV projections (masked K/V block skip)
    dim3 gqkv(3 * DD / 128, MTOK / 128);   // (24, 32)
    gemm_qkv<<<gqkv, 256, GSM_TOTAL>>>(bq, bk, bv, kpm);

    // Attention: 64 queries per block (R8 config), kt clamped by g_ktlim
    dim3 gattn(SS / 64, BH);               // (32, 32)
    attn_h<<<gattn, 128, ASM_TOTAL>>>(kpm);

    // Output projection
    dim3 gout(DD / 128, MTOK / 128);       // (8, 32)
    gemm_out<<<gout, 256, GSM_TOTAL>>>(bo, out);
}

// round 15
// speedup vs baseline: 1.0126x; 1.0126x over previous
#include <cuda_runtime.h>
#include <cuda_fp16.h>
#include <math.h>
#include <float.h>
#include <stdint.h>

// Problem dims (fixed by the reference)
#define BB  2
#define SS  2048
#define DD  1024
#define HH  16
#define HD  64
#define BH  (BB*HH)          // 32
#define MTOK (BB*SS)         // 4096

// Scratch (device globals: allocation-free rule)
__device__ __half g_Qh[BH*SS*HD];   // [bh][s][hd] (half, pre-scaled by 0.125*log2e)
__device__ __half g_Kh[BH*SS*HD];
__device__ __half g_Vh[BH*SS*HD];
__device__ __half g_Oh[MTOK*DD];    // [tok][d] attn out (half)
__device__ __half g_Xh[MTOK*DD];    // X rounded to half
__device__ __half g_Wqh[DD*DD], g_Wkh[DD*DD], g_Wvh[DD*DD], g_Woh[DD*DD];

// ---------------------------------------------------------------------------
// Helpers
// ---------------------------------------------------------------------------
__device__ __forceinline__ float ex2(float x) {
    float y; asm("ex2.approx.f32 %0, %1;" : "=f"(y) : "f"(x)); return y;
}
__device__ __forceinline__ uint32_t smem_u32(const void* p) {
    uint32_t a;
    asm("{ .reg .u64 t; cvta.to.shared.u64 t, %1; cvt.u32.u64 %0, t; }" : "=r"(a) : "l"(p));
    return a;
}
__device__ __forceinline__ void cpa16(uint32_t dst, const void* src) {
    asm volatile("{ .reg .u64 g; cvta.to.global.u64 g, %1; cp.async.cg.shared.global [%0], [g], 16; }"
                 :: "r"(dst), "l"(src));
}
#define CPA_COMMIT() asm volatile("cp.async.commit_group;" ::: "memory")
#define CPA_WAIT0()  asm volatile("cp.async.wait_group 0;" ::: "memory")
#define CPA_WAIT1()  asm volatile("cp.async.wait_group 1;" ::: "memory")

// swizzled byte address: 128B rows, 16B chunks, chunk ^= row&7
__device__ __forceinline__ uint32_t swz(uint32_t base, int row, int chunk) {
    return base + (uint32_t)(row * 128) + (uint32_t)(((chunk ^ (row & 7)) << 4));
}

__device__ __forceinline__ void ldm_x4(uint32_t& r0, uint32_t& r1, uint32_t& r2, uint32_t& r3, uint32_t a) {
    asm volatile("ldmatrix.sync.aligned.m8n8.x4.shared.b16 {%0,%1,%2,%3}, [%4];"
                 : "=r"(r0), "=r"(r1), "=r"(r2), "=r"(r3) : "r"(a));
}
__device__ __forceinline__ void ldm_x4t(uint32_t& r0, uint32_t& r1, uint32_t& r2, uint32_t& r3, uint32_t a) {
    asm volatile("ldmatrix.sync.aligned.m8n8.x4.trans.shared.b16 {%0,%1,%2,%3}, [%4];"
                 : "=r"(r0), "=r"(r1), "=r"(r2), "=r"(r3) : "r"(a));
}

// D += A * B  (m16n8k16 fp16 inputs, f32 accum)
__device__ __forceinline__ void mma_f16(float* d, const uint32_t* a, uint32_t b0, uint32_t b1) {
    asm volatile(
        "mma.sync.aligned.m16n8k16.row.col.f32.f16.f16.f32 "
        "{%0,%1,%2,%3},{%4,%5,%6,%7},{%8,%9},{%0,%1,%2,%3};"
        : "+f"(d[0]), "+f"(d[1]), "+f"(d[2]), "+f"(d[3])
        : "r"(a[0]), "r"(a[1]), "r"(a[2]), "r"(a[3]), "r"(b0), "r"(b1));
}

__device__ __forceinline__ uint32_t pack_h2(float lo, float hi) {
    __half2 h = __floats2half2_rn(lo, hi);
    return *(uint32_t*)&h;
}

// ---------------------------------------------------------------------------
// Prepass: convert X + 4 weight matrices to half (one launch).
// ---------------------------------------------------------------------------
#define XQUAD (MTOK*DD/4)      // 1048576
#define WQUAD (DD*DD/4)        // 262144
__global__ void prep_h(const float* __restrict__ X,
                       const float* __restrict__ wq, const float* __restrict__ wk,
                       const float* __restrict__ wv, const float* __restrict__ wo)
{
    const int i = blockIdx.x * blockDim.x + threadIdx.x;   // 0 .. XQUAD+4*WQUAD-1
    const float* s; __half* d; int loc;
    if (i < XQUAD) { s = X; d = g_Xh; loc = i; }
    else {
        const int j = i - XQUAD;
        const int reg = j >> 18;
        loc = j & (WQUAD - 1);
        s = (reg == 0) ? wq : (reg == 1) ? wk : (reg == 2) ? wv : wo;
        d = (reg == 0) ? g_Wqh : (reg == 1) ? g_Wkh : (reg == 2) ? g_Wvh : g_Woh;
    }
    float4 v = ((const float4*)s)[loc];
    uint2 u;
    u.x = pack_h2(v.x, v.y);
    u.y = pack_h2(v.z, v.w);
    ((uint2*)d)[loc] = u;
}

// ---------------------------------------------------------------------------
// fp16 NT GEMM (R8 config — measured best): C[m][n] = sum_k A[m][k]*W[n][k] + bias[n]
// Block 128x128, k-chunk 64 halves (128B swizzled rows), 3-stage cp.async.
// 256 thr = 8 warps (4m x 2n), warp tile 32x64. ldmatrix operand loads.
// HEADOUT 0: fp32 row-major.  1: half head-major.  2: half head-major *qscale.
// ---------------------------------------------------------------------------
#define GST  16384u                    // one matrix per stage: 128*128B
#define GSTG 32768u
#define GSM_TOTAL (3 * 32768)          // 98304

template<int HEADOUT>
__device__ __forceinline__ void gemm_body(
    const __half* __restrict__ A, const __half* __restrict__ W,
    const float* __restrict__ bias, void* __restrict__ Cout,
    int m0, int n0, char* smem)
{
    const uint32_t sb = smem_u32(smem);
    const int tid  = threadIdx.x;
    const int warp = tid >> 5;
    const int lane = tid & 31;
    const int r = lane >> 2;
    const int c = lane & 3;
    const int wm = (warp & 3) * 32;
    const int wn = (warp >> 2) * 64;
    const int lrow = (lane & 7) + (lane & 8);   // ldmatrix row-within-16 for this lane
    const int lsel = lane >> 4;                 // ldmatrix chunk-half select

    float acc[2][8][4];
#pragma unroll
    for (int mt = 0; mt < 2; mt++)
#pragma unroll
        for (int nt = 0; nt < 8; nt++)
#pragma unroll
            for (int i = 0; i < 4; i++) acc[mt][nt][i] = 0.f;

    auto fill = [&](int st, int k0) {
        const uint32_t base = sb + (uint32_t)st * GSTG;
#pragma unroll
        for (int t = 0; t < 4; t++) {
            const int idx = tid + t * 256;     // 0..1023
            const int row = idx >> 3;          // 0..127
            const int ch  = idx & 7;           // 16B chunk = 8 halves
            cpa16(swz(base, row, ch),       A + (size_t)(m0 + row) * DD + k0 + ch * 8);
            cpa16(swz(base + GST, row, ch), W + (size_t)(n0 + row) * DD + k0 + ch * 8);
        }
        CPA_COMMIT();
    };

    fill(0, 0);
    fill(1, 64);

    int st = 0, st2 = 2;
    for (int i = 0; i < 16; i++) {
        if (i + 1 < 16) { CPA_WAIT1(); } else { CPA_WAIT0(); }
        __syncthreads();
        if (i + 2 < 16) fill(st2, (i + 2) * 64);

        const uint32_t Ab = sb + (uint32_t)st * GSTG;
        const uint32_t Bb = Ab + GST;

#pragma unroll
        for (int ks = 0; ks < 4; ks++) {       // 4 x k16
            const int ch = ks * 2 + lsel;
            uint32_t af[2][4];
#pragma unroll
            for (int mt = 0; mt < 2; mt++)
                ldm_x4(af[mt][0], af[mt][1], af[mt][2], af[mt][3],
                       swz(Ab, wm + mt * 16 + lrow, ch));
            uint32_t bf[8][2];
#pragma unroll
            for (int np = 0; np < 4; np++) {
                uint32_t r0, r1, r2, r3;
                ldm_x4(r0, r1, r2, r3, swz(Bb, wn + np * 16 + lrow, ch));
                bf[2*np][0] = r0; bf[2*np][1] = r2;
                bf[2*np+1][0] = r1; bf[2*np+1][1] = r3;
            }
#pragma unroll
            for (int mt = 0; mt < 2; mt++)
#pragma unroll
                for (int nt = 0; nt < 8; nt++)
                    mma_f16(acc[mt][nt], af[mt], bf[nt][0], bf[nt][1]);
        }
        st  = (st  == 2) ? 0 : st  + 1;
        st2 = (st2 == 2) ? 0 : st2 + 1;
    }

#pragma unroll
    for (int mt = 0; mt < 2; mt++) {
        const int m_lo = m0 + wm + mt * 16 + r;
        const int m_hi = m_lo + 8;
#pragma unroll
        for (int nt = 0; nt < 8; nt++) {
            const int ng = n0 + wn + nt * 8 + 2 * c;
            const float b0 = bias[ng], b1 = bias[ng + 1];
            if (HEADOUT) {
                const float sc = (HEADOUT == 2) ? 0.18033688011112042f : 1.f;  // 0.125*log2(e)
                const uint32_t lo = pack_h2((acc[mt][nt][0] + b0) * sc, (acc[mt][nt][1] + b1) * sc);
                const uint32_t hi = pack_h2((acc[mt][nt][2] + b0) * sc, (acc[mt][nt][3] + b1) * sc);
                const int h  = ng >> 6;
                const int hd = ng & 63;
                const int blo = m_lo >> 11, slo = m_lo & 2047;
                const int bhi = m_hi >> 11, shi = m_hi & 2047;
                __half* Ch = (__half*)Cout;
                *(uint32_t*)&Ch[(((size_t)(blo * HH + h) * SS) + slo) * HD + hd] = lo;
                *(uint32_t*)&Ch[(((size_t)(bhi * HH + h) * SS) + shi) * HD + hd] = hi;
            } else {
                float* Cf = (float*)Cout;
                *(float2*)&Cf[(size_t)m_lo * DD + ng] = make_float2(acc[mt][nt][0] + b0, acc[mt][nt][1] + b1);
                *(float2*)&Cf[(size_t)m_hi * DD + ng] = make_float2(acc[mt][nt][2] + b0, acc[mt][nt][3] + b1);
            }
        }
    }
}

// Fused QKV: grid (24, 32); virtual n picks matrix. Q scaled.
// K/V blocks whose 128 tokens are ALL mask-padded are skipped (validated R12/R13).
__global__ __launch_bounds__(256, 2)
void gemm_qkv(const float* __restrict__ bq, const float* __restrict__ bk,
              const float* __restrict__ bv, const int* __restrict__ kpm)
{
    extern __shared__ char smem[];
    const int n0v   = blockIdx.x * 128;
    const int which = n0v >> 10;
    const int n0    = n0v & 1023;
    const int m0    = blockIdx.y * 128;
    if (which != 0) {
        const int b_ = m0 >> 11;
        const int s_ = m0 & 2047;
        const int pv = kpm[(size_t)b_ * SS + s_ + (threadIdx.x & 127)];
        if (__syncthreads_and(pv != 0)) return;   // all 128 tokens padded
    }
    if (which == 0)
        gemm_body<2>(g_Xh, g_Wqh, bq, g_Qh, m0, n0, smem);
    else if (which == 1)
        gemm_body<1>(g_Xh, g_Wkh, bk, g_Kh, m0, n0, smem);
    else
        gemm_body<1>(g_Xh, g_Wvh, bv, g_Vh, m0, n0, smem);
}

// Output projection: A = g_Oh, exact fp32 out.
__global__ __launch_bounds__(256, 2)
void gemm_out(const float* __restrict__ bo, float* __restrict__ Cout)
{
    extern __shared__ char smem[];
    gemm_body<0>(g_Oh, g_Woh, bo, Cout, blockIdx.y * 128, blockIdx.x * 128, smem);
}

// ---------------------------------------------------------------------------
// Flash attention, fp16 mma + ldmatrix, 64-key tiles, 2-stage cp.async,
// base-2 softmax. Block: 64 q rows of one (b,h), 128 thr = 4 warps x 16 rows.
// R13 config, occupancy raised 3 -> 4 blocks/SM (smem 4x41.5KB fits; regs
// forced to 128 — live state ~125 so no hot-loop spills expected).
// ---------------------------------------------------------------------------
#define AKOFF 0u
#define AVOFF 8192u
#define AMOFF 16384u
#define ASTG  16640u
#define APOFF 33280u
#define ASM_TOTAL (33280 + 8192)    // 41472

__global__ __launch_bounds__(128, 4)
void attn_h(const int* __restrict__ kpm)
{
    extern __shared__ char smem[];
    const uint32_t sb = smem_u32(smem);

    const int qt = gridDim.x - 1 - blockIdx.x;   // heavy causal blocks first
    const int bh = blockIdx.y;
    const int b_ = bh >> 4;
    const int h  = bh & 15;
    const int tid  = threadIdx.x;
    const int warp = tid >> 5;
    const int lane = tid & 31;
    const int r = lane >> 2;
    const int c = lane & 3;
    const int lrow = (lane & 7) + (lane & 8);
    const int lsel = lane >> 4;
    const int q0 = qt * 64;
    const int qr = warp * 16;
    const int qg_lo = q0 + qr + r;
    const int qg_hi = qg_lo + 8;

    auto fill = [&](int st, int kt) {
        const int kbase = kt * 64;
        const uint32_t base = sb + (uint32_t)st * ASTG;
#pragma unroll
        for (int i = 0; i < 4; i++) {
            const int idx = tid + i * 128;   // 0..511
            const int kr  = idx >> 3;        // 0..63
            const int ch  = idx & 7;
            cpa16(swz(base + AKOFF, kr, ch), g_Kh + (size_t)(bh * SS + kbase + kr) * HD + ch * 8);
            cpa16(swz(base + AVOFF, kr, ch), g_Vh + (size_t)(bh * SS + kbase + kr) * HD + ch * 8);
        }
        if (tid < 16)
            cpa16(base + AMOFF + tid * 16, kpm + (size_t)b_ * SS + kbase + tid * 4);
        CPA_COMMIT();
    };

    // Q fragments (half, pre-scaled): qf[ks][0..3] for k16 steps
    uint32_t qf[4][4];
    {
        const __half* qlo = g_Qh + (size_t)(bh * SS + qg_lo) * HD;
        const __half* qhi = g_Qh + (size_t)(bh * SS + qg_hi) * HD;
#pragma unroll
        for (int ks = 0; ks < 4; ks++) {
            qf[ks][0] = *(const uint32_t*)&qlo[ks * 16 + 2 * c];
            qf[ks][1] = *(const uint32_t*)&qhi[ks * 16 + 2 * c];
            qf[ks][2] = *(const uint32_t*)&qlo[ks * 16 + 2 * c + 8];
            qf[ks][3] = *(const uint32_t*)&qhi[ks * 16 + 2 * c + 8];
        }
    }

    float o[8][4];
#pragma unroll
    for (int nt = 0; nt < 8; nt++)
#pragma unroll
        for (int i = 0; i < 4; i++) o[nt][i] = 0.f;
    float m_lo = -1e30f, m_hi = -1e30f, l_lo = 0.f, l_hi = 0.f;

    const int kt_max = qt;
    fill(0, 0);

    for (int kt = 0; kt <= kt_max; kt++) {
        CPA_WAIT0();
        __syncthreads();
        if (kt + 1 <= kt_max) fill((kt + 1) & 1, kt + 1);

        const uint32_t base = sb + (uint32_t)(kt & 1) * ASTG;
        const uint32_t Kb = base + AKOFF;
        const uint32_t Vb = base + AVOFF;
        const int* mk = (const int*)(smem + (kt & 1) * ASTG + AMOFF);
        const uint32_t Pb = sb + APOFF;

        const int kbase = kt * 64;
        const bool mymask = (mk[lane] != 0) || (mk[lane + 32] != 0);
        const int  skip = __all_sync(0xffffffffu, (mk[lane] != 0) && (mk[lane + 32] != 0));
        const int  anym = __any_sync(0xffffffffu, mymask);

        if (!skip) {
            // ---- scores: S = Q K^T (log2 domain) ----
            float s[8][4];
#pragma unroll
            for (int nt = 0; nt < 8; nt++)
#pragma unroll
                for (int i = 0; i < 4; i++) s[nt][i] = 0.f;
#pragma unroll
            for (int ks = 0; ks < 4; ks++) {
                const int ch = ks * 2 + lsel;
                uint32_t bf[8][2];
#pragma unroll
                for (int np = 0; np < 4; np++) {
                    uint32_t r0, r1, r2, r3;
                    ldm_x4(r0, r1, r2, r3, swz(Kb, np * 16 + lrow, ch));
                    bf[2*np][0] = r0; bf[2*np][1] = r2;
                    bf[2*np+1][0] = r1; bf[2*np+1][1] = r3;
                }
#pragma unroll
                for (int nt = 0; nt < 8; nt++)
                    mma_f16(s[nt], qf[ks], bf[nt][0], bf[nt][1]);
            }

            // ---- mask + row max ----
            float mloc_lo = -1e30f, mloc_hi = -1e30f;
            if (kt < qt && !anym) {
#pragma unroll
                for (int nt = 0; nt < 8; nt++) {
                    mloc_lo = fmaxf(mloc_lo, fmaxf(s[nt][0], s[nt][1]));
                    mloc_hi = fmaxf(mloc_hi, fmaxf(s[nt][2], s[nt][3]));
                }
            } else {
#pragma unroll
                for (int nt = 0; nt < 8; nt++) {
                    const int kc0 = nt * 8 + 2 * c;
                    const bool bad0 = mk[kc0] != 0;
                    const bool bad1 = mk[kc0 + 1] != 0;
                    const int kg0 = kbase + kc0, kg1 = kg0 + 1;
                    s[nt][0] = (bad0 || kg0 > qg_lo) ? -1e30f : s[nt][0];
                    s[nt][1] = (bad1 || kg1 > qg_lo) ? -1e30f : s[nt][1];
                    s[nt][2] = (bad0 || kg0 > qg_hi) ? -1e30f : s[nt][2];
                    s[nt][3] = (bad1 || kg1 > qg_hi) ? -1e30f : s[nt][3];
                    mloc_lo = fmaxf(mloc_lo, fmaxf(s[nt][0], s[nt][1]));
                    mloc_hi = fmaxf(mloc_hi, fmaxf(s[nt][2], s[nt][3]));
                }
            }
            mloc_lo = fmaxf(mloc_lo, __shfl_xor_sync(0xffffffffu, mloc_lo, 1));
            mloc_lo = fmaxf(mloc_lo, __shfl_xor_sync(0xffffffffu, mloc_lo, 2));
            mloc_hi = fmaxf(mloc_hi, __shfl_xor_sync(0xffffffffu, mloc_hi, 1));
            mloc_hi = fmaxf(mloc_hi, __shfl_xor_sync(0xffffffffu, mloc_hi, 2));

            const float mn_lo = fmaxf(m_lo, mloc_lo);
            const float mn_hi = fmaxf(m_hi, mloc_hi);
            const float a_lo = ex2(m_lo - mn_lo);
            const float a_hi = ex2(m_hi - mn_hi);
            m_lo = mn_lo; m_hi = mn_hi;

            // exp2 + row sums + P -> half in smem (swizzled, ldmatrix layout)
            float ps_lo = 0.f, ps_hi = 0.f;
#pragma unroll
            for (int nt = 0; nt < 8; nt++) {
                s[nt][0] = ex2(s[nt][0] - mn_lo);
                s[nt][1] = ex2(s[nt][1] - mn_lo);
                s[nt][2] = ex2(s[nt][2] - mn_hi);
                s[nt][3] = ex2(s[nt][3] - mn_hi);
                ps_lo += s[nt][0] + s[nt][1];
                ps_hi += s[nt][2] + s[nt][3];
                const int row0 = qr + r, row1 = qr + r + 8;
                *(uint32_t*)(smem + (swz(Pb, row0, nt) - sb) + 4 * c) = pack_h2(s[nt][0], s[nt][1]);
                *(uint32_t*)(smem + (swz(Pb, row1, nt) - sb) + 4 * c) = pack_h2(s[nt][2], s[nt][3]);
            }
            ps_lo += __shfl_xor_sync(0xffffffffu, ps_lo, 1);
            ps_lo += __shfl_xor_sync(0xffffffffu, ps_lo, 2);
            ps_hi += __shfl_xor_sync(0xffffffffu, ps_hi, 1);
            ps_hi += __shfl_xor_sync(0xffffffffu, ps_hi, 2);
            l_lo = a_lo * l_lo + ps_lo;
            l_hi = a_hi * l_hi + ps_hi;

#pragma unroll
            for (int nt = 0; nt < 8; nt++) {
                o[nt][0] *= a_lo; o[nt][1] *= a_lo;
                o[nt][2] *= a_hi; o[nt][3] *= a_hi;
            }
            __syncwarp();

            // ---- O += P V ----
#pragma unroll
            for (int ks = 0; ks < 4; ks++) {
                uint32_t af[4];
                ldm_x4(af[0], af[1], af[2], af[3],
                       swz(Pb, qr + lrow, ks * 2 + lsel));
                uint32_t bf[8][2];
#pragma unroll
                for (int np = 0; np < 4; np++) {
                    uint32_t r0, r1, r2, r3;
                    ldm_x4t(r0, r1, r2, r3,
                            swz(Vb, ks * 16 + lrow, 2 * np + lsel));
                    bf[2*np][0] = r0; bf[2*np][1] = r1;
                    bf[2*np+1][0] = r2; bf[2*np+1][1] = r3;
                }
#pragma unroll
                for (int nt = 0; nt < 8; nt++)
                    mma_f16(o[nt], af, bf[nt][0], bf[nt][1]);
            }
            __syncwarp();
        }
    }

    // ---- epilogue: normalize, convert to half, store head-major into g_Oh ----
    const float inv_lo = 1.f / l_lo;
    const float inv_hi = 1.f / l_hi;
    __half* olo = g_Oh + (size_t)(b_ * SS + qg_lo) * DD + h * HD;
    __half* ohi = g_Oh + (size_t)(b_ * SS + qg_hi) * DD + h * HD;
#pragma unroll
    for (int nt = 0; nt < 8; nt++) {
        const int dc = nt * 8 + 2 * c;
        *(uint32_t*)&olo[dc] = pack_h2(o[nt][0] * inv_lo, o[nt][1] * inv_lo);
        *(uint32_t*)&ohi[dc] = pack_h2(o[nt][2] * inv_hi, o[nt][3] * inv_hi);
    }
}

// ---------------------------------------------------------------------------
// Launch
// Inputs: 0:X 1:key_padding_mask 2:Wq 3:bq 4:Wk 5:bk 6:Wv 7:bv 8:Wo 9:bo
// ---------------------------------------------------------------------------
extern "C" void kernel_launch(void* const* d_in, const int* in_sizes, int n_in,
                              void* d_out, int out_size)
{
    const float* X   = (const float*)d_in[0];
    const int*   kpm = (const int*)  d_in[1];
    const float* Wq  = (const float*)d_in[2];
    const float* bq  = (const float*)d_in[3];
    const float* Wk  = (const float*)d_in[4];
    const float* bk  = (const float*)d_in[5];
    const float* Wv  = (const float*)d_in[6];
    const float* bv  = (const float*)d_in[7];
    const float* Wo  = (const float*)d_in[8];
    const float* bo  = (const float*)d_in[9];
    float* out = (float*)d_out;

    cudaFuncSetAttribute(gemm_qkv, cudaFuncAttributeMaxDynamicSharedMemorySize, GSM_TOTAL);
    cudaFuncSetAttribute(gemm_out, cudaFuncAttributeMaxDynamicSharedMemorySize, GSM_TOTAL);
    cudaFuncSetAttribute(attn_h,   cudaFuncAttributeMaxDynamicSharedMemorySize, ASM_TOTAL);

    // Prepass: X + 4 weights -> half
    prep_h<<<(XQUAD + 4 * WQUAD) / 256, 256>>>(X, Wq, Wk, Wv, Wo);

    // Fused QKV projections (masked K/V block skip)
    dim3 gqkv(3 * DD / 128, MTOK / 128);   // (24, 32)
    gemm_qkv<<<gqkv, 256, GSM_TOTAL>>>(bq, bk, bv, kpm);

    // Attention: 64 queries per block, 4 blocks/SM
    dim3 gattn(SS / 64, BH);               // (32, 32)
    attn_h<<<gattn, 128, ASM_TOTAL>>>(kpm);

    // Output projection
    dim3 gout(DD / 128, MTOK / 128);       // (8, 32)
    gemm_out<<<gout, 256, GSM_TOTAL>>>(bo, out);
}

// round 16
// speedup vs baseline: 1.0863x; 1.0728x over previous
#include <cuda_runtime.h>
#include <cuda_fp16.h>
#include <math.h>
#include <float.h>
#include <stdint.h>

// Problem dims (fixed by the reference)
#define BB  2
#define SS  2048
#define DD  1024
#define HH  16
#define HD  64
#define BH  (BB*HH)          // 32
#define MTOK (BB*SS)         // 4096

// Scratch (device globals: allocation-free rule)
__device__ __half g_Qh[BH*SS*HD];   // [bh][s][hd] (half, pre-scaled by 0.125*log2e)
__device__ __half g_Kh[BH*SS*HD];
__device__ __half g_Vh[BH*SS*HD];
__device__ __half g_Oh[MTOK*DD];    // [tok][d] attn out (half)
__device__ __half g_Xh[MTOK*DD];    // X rounded to half
__device__ __half g_Wqh[DD*DD], g_Wkh[DD*DD], g_Wvh[DD*DD], g_Woh[DD*DD];

// ---------------------------------------------------------------------------
// Helpers
// ---------------------------------------------------------------------------
__device__ __forceinline__ float ex2(float x) {
    float y; asm("ex2.approx.f32 %0, %1;" : "=f"(y) : "f"(x)); return y;
}
__device__ __forceinline__ uint32_t smem_u32(const void* p) {
    uint32_t a;
    asm("{ .reg .u64 t; cvta.to.shared.u64 t, %1; cvt.u32.u64 %0, t; }" : "=r"(a) : "l"(p));
    return a;
}
__device__ __forceinline__ void cpa16(uint32_t dst, const void* src) {
    asm volatile("{ .reg .u64 g; cvta.to.global.u64 g, %1; cp.async.cg.shared.global [%0], [g], 16; }"
                 :: "r"(dst), "l"(src));
}
#define CPA_COMMIT() asm volatile("cp.async.commit_group;" ::: "memory")
#define CPA_WAIT0()  asm volatile("cp.async.wait_group 0;" ::: "memory")
#define CPA_WAIT1()  asm volatile("cp.async.wait_group 1;" ::: "memory")

// swizzled byte address: 128B rows, 16B chunks, chunk ^= row&7
__device__ __forceinline__ uint32_t swz(uint32_t base, int row, int chunk) {
    return base + (uint32_t)(row * 128) + (uint32_t)(((chunk ^ (row & 7)) << 4));
}

__device__ __forceinline__ void ldm_x4(uint32_t& r0, uint32_t& r1, uint32_t& r2, uint32_t& r3, uint32_t a) {
    asm volatile("ldmatrix.sync.aligned.m8n8.x4.shared.b16 {%0,%1,%2,%3}, [%4];"
                 : "=r"(r0), "=r"(r1), "=r"(r2), "=r"(r3) : "r"(a));
}
__device__ __forceinline__ void ldm_x4t(uint32_t& r0, uint32_t& r1, uint32_t& r2, uint32_t& r3, uint32_t a) {
    asm volatile("ldmatrix.sync.aligned.m8n8.x4.trans.shared.b16 {%0,%1,%2,%3}, [%4];"
                 : "=r"(r0), "=r"(r1), "=r"(r2), "=r"(r3) : "r"(a));
}

// D += A * B  (m16n8k16 fp16 inputs, f32 accum)
__device__ __forceinline__ void mma_f16(float* d, const uint32_t* a, uint32_t b0, uint32_t b1) {
    asm volatile(
        "mma.sync.aligned.m16n8k16.row.col.f32.f16.f16.f32 "
        "{%0,%1,%2,%3},{%4,%5,%6,%7},{%8,%9},{%0,%1,%2,%3};"
        : "+f"(d[0]), "+f"(d[1]), "+f"(d[2]), "+f"(d[3])
        : "r"(a[0]), "r"(a[1]), "r"(a[2]), "r"(a[3]), "r"(b0), "r"(b1));
}

__device__ __forceinline__ uint32_t pack_h2(float lo, float hi) {
    __half2 h = __floats2half2_rn(lo, hi);
    return *(uint32_t*)&h;
}

// ---------------------------------------------------------------------------
// Prepass: convert X + 4 weight matrices to half (one launch).
// ---------------------------------------------------------------------------
#define XQUAD (MTOK*DD/4)      // 1048576
#define WQUAD (DD*DD/4)        // 262144
__global__ void prep_h(const float* __restrict__ X,
                       const float* __restrict__ wq, const float* __restrict__ wk,
                       const float* __restrict__ wv, const float* __restrict__ wo)
{
    const int i = blockIdx.x * blockDim.x + threadIdx.x;   // 0 .. XQUAD+4*WQUAD-1
    const float* s; __half* d; int loc;
    if (i < XQUAD) { s = X; d = g_Xh; loc = i; }
    else {
        const int j = i - XQUAD;
        const int reg = j >> 18;
        loc = j & (WQUAD - 1);
        s = (reg == 0) ? wq : (reg == 1) ? wk : (reg == 2) ? wv : wo;
        d = (reg == 0) ? g_Wqh : (reg == 1) ? g_Wkh : (reg == 2) ? g_Wvh : g_Woh;
    }
    float4 v = ((const float4*)s)[loc];
    uint2 u;
    u.x = pack_h2(v.x, v.y);
    u.y = pack_h2(v.z, v.w);
    ((uint2*)d)[loc] = u;
}

// ---------------------------------------------------------------------------
// fp16 NT GEMM (R8 config — measured best): C[m][n] = sum_k A[m][k]*W[n][k] + bias[n]
// Block 128x128, k-chunk 64 halves (128B swizzled rows), 3-stage cp.async.
// 256 thr = 8 warps (4m x 2n), warp tile 32x64. ldmatrix operand loads.
// HEADOUT 0: fp32 row-major.  1: half head-major.  2: half head-major *qscale.
// ---------------------------------------------------------------------------
#define GST  16384u                    // one matrix per stage: 128*128B
#define GSTG 32768u
#define GSM_TOTAL (3 * 32768)          // 98304

template<int HEADOUT>
__device__ __forceinline__ void gemm_body(
    const __half* __restrict__ A, const __half* __restrict__ W,
    const float* __restrict__ bias, void* __restrict__ Cout,
    int m0, int n0, char* smem)
{
    const uint32_t sb = smem_u32(smem);
    const int tid  = threadIdx.x;
    const int warp = tid >> 5;
    const int lane = tid & 31;
    const int r = lane >> 2;
    const int c = lane & 3;
    const int wm = (warp & 3) * 32;
    const int wn = (warp >> 2) * 64;
    const int lrow = (lane & 7) + (lane & 8);   // ldmatrix row-within-16 for this lane
    const int lsel = lane >> 4;                 // ldmatrix chunk-half select

    float acc[2][8][4];
#pragma unroll
    for (int mt = 0; mt < 2; mt++)
#pragma unroll
        for (int nt = 0; nt < 8; nt++)
#pragma unroll
            for (int i = 0; i < 4; i++) acc[mt][nt][i] = 0.f;

    auto fill = [&](int st, int k0) {
        const uint32_t base = sb + (uint32_t)st * GSTG;
#pragma unroll
        for (int t = 0; t < 4; t++) {
            const int idx = tid + t * 256;     // 0..1023
            const int row = idx >> 3;          // 0..127
            const int ch  = idx & 7;           // 16B chunk = 8 halves
            cpa16(swz(base, row, ch),       A + (size_t)(m0 + row) * DD + k0 + ch * 8);
            cpa16(swz(base + GST, row, ch), W + (size_t)(n0 + row) * DD + k0 + ch * 8);
        }
        CPA_COMMIT();
    };

    fill(0, 0);
    fill(1, 64);

    int st = 0, st2 = 2;
    for (int i = 0; i < 16; i++) {
        if (i + 1 < 16) { CPA_WAIT1(); } else { CPA_WAIT0(); }
        __syncthreads();
        if (i + 2 < 16) fill(st2, (i + 2) * 64);

        const uint32_t Ab = sb + (uint32_t)st * GSTG;
        const uint32_t Bb = Ab + GST;

#pragma unroll
        for (int ks = 0; ks < 4; ks++) {       // 4 x k16
            const int ch = ks * 2 + lsel;
            uint32_t af[2][4];
#pragma unroll
            for (int mt = 0; mt < 2; mt++)
                ldm_x4(af[mt][0], af[mt][1], af[mt][2], af[mt][3],
                       swz(Ab, wm + mt * 16 + lrow, ch));
            uint32_t bf[8][2];
#pragma unroll
            for (int np = 0; np < 4; np++) {
                uint32_t r0, r1, r2, r3;
                ldm_x4(r0, r1, r2, r3, swz(Bb, wn + np * 16 + lrow, ch));
                bf[2*np][0] = r0; bf[2*np][1] = r2;
                bf[2*np+1][0] = r1; bf[2*np+1][1] = r3;
            }
#pragma unroll
            for (int mt = 0; mt < 2; mt++)
#pragma unroll
                for (int nt = 0; nt < 8; nt++)
                    mma_f16(acc[mt][nt], af[mt], bf[nt][0], bf[nt][1]);
        }
        st  = (st  == 2) ? 0 : st  + 1;
        st2 = (st2 == 2) ? 0 : st2 + 1;
    }

#pragma unroll
    for (int mt = 0; mt < 2; mt++) {
        const int m_lo = m0 + wm + mt * 16 + r;
        const int m_hi = m_lo + 8;
#pragma unroll
        for (int nt = 0; nt < 8; nt++) {
            const int ng = n0 + wn + nt * 8 + 2 * c;
            const float b0 = bias[ng], b1 = bias[ng + 1];
            if (HEADOUT) {
                const float sc = (HEADOUT == 2) ? 0.18033688011112042f : 1.f;  // 0.125*log2(e)
                const uint32_t lo = pack_h2((acc[mt][nt][0] + b0) * sc, (acc[mt][nt][1] + b1) * sc);
                const uint32_t hi = pack_h2((acc[mt][nt][2] + b0) * sc, (acc[mt][nt][3] + b1) * sc);
                const int h  = ng >> 6;
                const int hd = ng & 63;
                const int blo = m_lo >> 11, slo = m_lo & 2047;
                const int bhi = m_hi >> 11, shi = m_hi & 2047;
                __half* Ch = (__half*)Cout;
                *(uint32_t*)&Ch[(((size_t)(blo * HH + h) * SS) + slo) * HD + hd] = lo;
                *(uint32_t*)&Ch[(((size_t)(bhi * HH + h) * SS) + shi) * HD + hd] = hi;
            } else {
                float* Cf = (float*)Cout;
                *(float2*)&Cf[(size_t)m_lo * DD + ng] = make_float2(acc[mt][nt][0] + b0, acc[mt][nt][1] + b1);
                *(float2*)&Cf[(size_t)m_hi * DD + ng] = make_float2(acc[mt][nt][2] + b0, acc[mt][nt][3] + b1);
            }
        }
    }
}

// Fused QKV: grid (24, 32); virtual n picks matrix. Q scaled.
// K/V blocks whose 128 tokens are ALL mask-padded are skipped (validated R12/R13).
__global__ __launch_bounds__(256, 2)
void gemm_qkv(const float* __restrict__ bq, const float* __restrict__ bk,
              const float* __restrict__ bv, const int* __restrict__ kpm)
{
    extern __shared__ char smem[];
    const int n0v   = blockIdx.x * 128;
    const int which = n0v >> 10;
    const int n0    = n0v & 1023;
    const int m0    = blockIdx.y * 128;
    if (which != 0) {
        const int b_ = m0 >> 11;
        const int s_ = m0 & 2047;
        const int pv = kpm[(size_t)b_ * SS + s_ + (threadIdx.x & 127)];
        if (__syncthreads_and(pv != 0)) return;   // all 128 tokens padded
    }
    if (which == 0)
        gemm_body<2>(g_Xh, g_Wqh, bq, g_Qh, m0, n0, smem);
    else if (which == 1)
        gemm_body<1>(g_Xh, g_Wkh, bk, g_Kh, m0, n0, smem);
    else
        gemm_body<1>(g_Xh, g_Wvh, bv, g_Vh, m0, n0, smem);
}

// Output projection: A = g_Oh, exact fp32 out.
__global__ __launch_bounds__(256, 2)
void gemm_out(const float* __restrict__ bo, float* __restrict__ Cout)
{
    extern __shared__ char smem[];
    gemm_body<0>(g_Oh, g_Woh, bo, Cout, blockIdx.y * 128, blockIdx.x * 128, smem);
}

// ---------------------------------------------------------------------------
// Flash attention, fp16 mma + ldmatrix, 64-key tiles, 2-stage cp.async,
// base-2 softmax. Block: 64 q rows of one (b,h), 128 thr = 4 warps x 16 rows,
// 4 blocks/SM. Grid = (bh, qt) with qt reversed: global LPT order — all 32
// heads' heaviest (qt=31) blocks enumerate first, then qt=30, ...
// ---------------------------------------------------------------------------
#define AKOFF 0u
#define AVOFF 8192u
#define AMOFF 16384u
#define ASTG  16640u
#define APOFF 33280u
#define ASM_TOTAL (33280 + 8192)    // 41472

__global__ __launch_bounds__(128, 4)
void attn_h(const int* __restrict__ kpm)
{
    extern __shared__ char smem[];
    const uint32_t sb = smem_u32(smem);

    const int qt = gridDim.y - 1 - blockIdx.y;   // heavy causal rows first (LPT)
    const int bh = blockIdx.x;
    const int b_ = bh >> 4;
    const int h  = bh & 15;
    const int tid  = threadIdx.x;
    const int warp = tid >> 5;
    const int lane = tid & 31;
    const int r = lane >> 2;
    const int c = lane & 3;
    const int lrow = (lane & 7) + (lane & 8);
    const int lsel = lane >> 4;
    const int q0 = qt * 64;
    const int qr = warp * 16;
    const int qg_lo = q0 + qr + r;
    const int qg_hi = qg_lo + 8;

    auto fill = [&](int st, int kt) {
        const int kbase = kt * 64;
        const uint32_t base = sb + (uint32_t)st * ASTG;
#pragma unroll
        for (int i = 0; i < 4; i++) {
            const int idx = tid + i * 128;   // 0..511
            const int kr  = idx >> 3;        // 0..63
            const int ch  = idx & 7;
            cpa16(swz(base + AKOFF, kr, ch), g_Kh + (size_t)(bh * SS + kbase + kr) * HD + ch * 8);
            cpa16(swz(base + AVOFF, kr, ch), g_Vh + (size_t)(bh * SS + kbase + kr) * HD + ch * 8);
        }
        if (tid < 16)
            cpa16(base + AMOFF + tid * 16, kpm + (size_t)b_ * SS + kbase + tid * 4);
        CPA_COMMIT();
    };

    // Q fragments (half, pre-scaled): qf[ks][0..3] for k16 steps
    uint32_t qf[4][4];
    {
        const __half* qlo = g_Qh + (size_t)(bh * SS + qg_lo) * HD;
        const __half* qhi = g_Qh + (size_t)(bh * SS + qg_hi) * HD;
#pragma unroll
        for (int ks = 0; ks < 4; ks++) {
            qf[ks][0] = *(const uint32_t*)&qlo[ks * 16 + 2 * c];
            qf[ks][1] = *(const uint32_t*)&qhi[ks * 16 + 2 * c];
            qf[ks][2] = *(const uint32_t*)&qlo[ks * 16 + 2 * c + 8];
            qf[ks][3] = *(const uint32_t*)&qhi[ks * 16 + 2 * c + 8];
        }
    }

    float o[8][4];
#pragma unroll
    for (int nt = 0; nt < 8; nt++)
#pragma unroll
        for (int i = 0; i < 4; i++) o[nt][i] = 0.f;
    float m_lo = -1e30f, m_hi = -1e30f, l_lo = 0.f, l_hi = 0.f;

    const int kt_max = qt;
    fill(0, 0);

    for (int kt = 0; kt <= kt_max; kt++) {
        CPA_WAIT0();
        __syncthreads();
        if (kt + 1 <= kt_max) fill((kt + 1) & 1, kt + 1);

        const uint32_t base = sb + (uint32_t)(kt & 1) * ASTG;
        const uint32_t Kb = base + AKOFF;
        const uint32_t Vb = base + AVOFF;
        const int* mk = (const int*)(smem + (kt & 1) * ASTG + AMOFF);
        const uint32_t Pb = sb + APOFF;

        const int kbase = kt * 64;
        const bool mymask = (mk[lane] != 0) || (mk[lane + 32] != 0);
        const int  skip = __all_sync(0xffffffffu, (mk[lane] != 0) && (mk[lane + 32] != 0));
        const int  anym = __any_sync(0xffffffffu, mymask);

        if (!skip) {
            // ---- scores: S = Q K^T (log2 domain) ----
            float s[8][4];
#pragma unroll
            for (int nt = 0; nt < 8; nt++)
#pragma unroll
                for (int i = 0; i < 4; i++) s[nt][i] = 0.f;
#pragma unroll
            for (int ks = 0; ks < 4; ks++) {
                const int ch = ks * 2 + lsel;
                uint32_t bf[8][2];
#pragma unroll
                for (int np = 0; np < 4; np++) {
                    uint32_t r0, r1, r2, r3;
                    ldm_x4(r0, r1, r2, r3, swz(Kb, np * 16 + lrow, ch));
                    bf[2*np][0] = r0; bf[2*np][1] = r2;
                    bf[2*np+1][0] = r1; bf[2*np+1][1] = r3;
                }
#pragma unroll
                for (int nt = 0; nt < 8; nt++)
                    mma_f16(s[nt], qf[ks], bf[nt][0], bf[nt][1]);
            }

            // ---- mask + row max ----
            float mloc_lo = -1e30f, mloc_hi = -1e30f;
            if (kt < qt && !anym) {
#pragma unroll
                for (int nt = 0; nt < 8; nt++) {
                    mloc_lo = fmaxf(mloc_lo, fmaxf(s[nt][0], s[nt][1]));
                    mloc_hi = fmaxf(mloc_hi, fmaxf(s[nt][2], s[nt][3]));
                }
            } else {
#pragma unroll
                for (int nt = 0; nt < 8; nt++) {
                    const int kc0 = nt * 8 + 2 * c;
                    const bool bad0 = mk[kc0] != 0;
                    const bool bad1 = mk[kc0 + 1] != 0;
                    const int kg0 = kbase + kc0, kg1 = kg0 + 1;
                    s[nt][0] = (bad0 || kg0 > qg_lo) ? -1e30f : s[nt][0];
                    s[nt][1] = (bad1 || kg1 > qg_lo) ? -1e30f : s[nt][1];
                    s[nt][2] = (bad0 || kg0 > qg_hi) ? -1e30f : s[nt][2];
                    s[nt][3] = (bad1 || kg1 > qg_hi) ? -1e30f : s[nt][3];
                    mloc_lo = fmaxf(mloc_lo, fmaxf(s[nt][0], s[nt][1]));
                    mloc_hi = fmaxf(mloc_hi, fmaxf(s[nt][2], s[nt][3]));
                }
            }
            mloc_lo = fmaxf(mloc_lo, __shfl_xor_sync(0xffffffffu, mloc_lo, 1));
            mloc_lo = fmaxf(mloc_lo, __shfl_xor_sync(0xffffffffu, mloc_lo, 2));
            mloc_hi = fmaxf(mloc_hi, __shfl_xor_sync(0xffffffffu, mloc_hi, 1));
            mloc_hi = fmaxf(mloc_hi, __shfl_xor_sync(0xffffffffu, mloc_hi, 2));

            const float mn_lo = fmaxf(m_lo, mloc_lo);
            const float mn_hi = fmaxf(m_hi, mloc_hi);
            const float a_lo = ex2(m_lo - mn_lo);
            const float a_hi = ex2(m_hi - mn_hi);
            m_lo = mn_lo; m_hi = mn_hi;

            // exp2 + row sums + P -> half in smem (swizzled, ldmatrix layout)
            float ps_lo = 0.f, ps_hi = 0.f;
#pragma unroll
            for (int nt = 0; nt < 8; nt++) {
                s[nt][0] = ex2(s[nt][0] - mn_lo);
                s[nt][1] = ex2(s[nt][1] - mn_lo);
                s[nt][2] = ex2(s[nt][2] - mn_hi);
                s[nt][3] = ex2(s[nt][3] - mn_hi);
                ps_lo += s[nt][0] + s[nt][1];
                ps_hi += s[nt][2] + s[nt][3];
                const int row0 = qr + r, row1 = qr + r + 8;
                *(uint32_t*)(smem + (swz(Pb, row0, nt) - sb) + 4 * c) = pack_h2(s[nt][0], s[nt][1]);
                *(uint32_t*)(smem + (swz(Pb, row1, nt) - sb) + 4 * c) = pack_h2(s[nt][2], s[nt][3]);
            }
            ps_lo += __shfl_xor_sync(0xffffffffu, ps_lo, 1);
            ps_lo += __shfl_xor_sync(0xffffffffu, ps_lo, 2);
            ps_hi += __shfl_xor_sync(0xffffffffu, ps_hi, 1);
            ps_hi += __shfl_xor_sync(0xffffffffu, ps_hi, 2);
            l_lo = a_lo * l_lo + ps_lo;
            l_hi = a_hi * l_hi + ps_hi;

#pragma unroll
            for (int nt = 0; nt < 8; nt++) {
                o[nt][0] *= a_lo; o[nt][1] *= a_lo;
                o[nt][2] *= a_hi; o[nt][3] *= a_hi;
            }
            __syncwarp();

            // ---- O += P V ----
#pragma unroll
            for (int ks = 0; ks < 4; ks++) {
                uint32_t af[4];
                ldm_x4(af[0], af[1], af[2], af[3],
                       swz(Pb, qr + lrow, ks * 2 + lsel));
                uint32_t bf[8][2];
#pragma unroll
                for (int np = 0; np < 4; np++) {
                    uint32_t r0, r1, r2, r3;
                    ldm_x4t(r0, r1, r2, r3,
                            swz(Vb, ks * 16 + lrow, 2 * np + lsel));
                    bf[2*np][0] = r0; bf[2*np][1] = r1;
                    bf[2*np+1][0] = r2; bf[2*np+1][1] = r3;
                }
#pragma unroll
                for (int nt = 0; nt < 8; nt++)
                    mma_f16(o[nt], af, bf[nt][0], bf[nt][1]);
            }
            __syncwarp();
        }
    }

    // ---- epilogue: normalize, convert to half, store head-major into g_Oh ----
    const float inv_lo = 1.f / l_lo;
    const float inv_hi = 1.f / l_hi;
    __half* olo = g_Oh + (size_t)(b_ * SS + qg_lo) * DD + h * HD;
    __half* ohi = g_Oh + (size_t)(b_ * SS + qg_hi) * DD + h * HD;
#pragma unroll
    for (int nt = 0; nt < 8; nt++) {
        const int dc = nt * 8 + 2 * c;
        *(uint32_t*)&olo[dc] = pack_h2(o[nt][0] * inv_lo, o[nt][1] * inv_lo);
        *(uint32_t*)&ohi[dc] = pack_h2(o[nt][2] * inv_hi, o[nt][3] * inv_hi);
    }
}

// ---------------------------------------------------------------------------
// Launch
// Inputs: 0:X 1:key_padding_mask 2:Wq 3:bq 4:Wk 5:bk 6:Wv 7:bv 8:Wo 9:bo
// ---------------------------------------------------------------------------
extern "C" void kernel_launch(void* const* d_in, const int* in_sizes, int n_in,
                              void* d_out, int out_size)
{
    const float* X   = (const float*)d_in[0];
    const int*   kpm = (const int*)  d_in[1];
    const float* Wq  = (const float*)d_in[2];
    const float* bq  = (const float*)d_in[3];
    const float* Wk  = (const float*)d_in[4];
    const float* bk  = (const float*)d_in[5];
    const float* Wv  = (const float*)d_in[6];
    const float* bv  = (const float*)d_in[7];
    const float* Wo  = (const float*)d_in[8];
    const float* bo  = (const float*)d_in[9];
    float* out = (float*)d_out;

    cudaFuncSetAttribute(gemm_qkv, cudaFuncAttributeMaxDynamicSharedMemorySize, GSM_TOTAL);
    cudaFuncSetAttribute(gemm_out, cudaFuncAttributeMaxDynamicSharedMemorySize, GSM_TOTAL);
    cudaFuncSetAttribute(attn_h,   cudaFuncAttributeMaxDynamicSharedMemorySize, ASM_TOTAL);

    // Prepass: X + 4 weights -> half
    prep_h<<<(XQUAD + 4 * WQUAD) / 256, 256>>>(X, Wq, Wk, Wv, Wo);

    // Fused QKV projections (masked K/V block skip)
    dim3 gqkv(3 * DD / 128, MTOK / 128);   // (24, 32)
    gemm_qkv<<<gqkv, 256, GSM_TOTAL>>>(bq, bk, bv, kpm);

    // Attention: grid (bh, qt) with qt reversed — global LPT order
    dim3 gattn(BH, SS / 64);               // (32, 32)
    attn_h<<<gattn, 128, ASM_TOTAL>>>(kpm);

    // Output projection
    dim3 gout(DD / 128, MTOK / 128);       // (8, 32)
    gemm_out<<<gout, 256, GSM_TOTAL>>>(bo, out);
}